// round 6
// baseline (speedup 1.0000x reference)
#include <cuda_runtime.h>
#include <cuda_bf16.h>
#include <math.h>
#include <stdint.h>

// ---- problem dims ----
#define Bb   16
#define Ll   512
#define Mm   32
#define PREDp 96
#define Pp   16
#define Sss  8
#define Dd   128
#define NSTn 16
#define DCc  4
#define NLl  4
#define Nn   63
#define DIi  256
#define DTRr 8
#define BMr  512
#define TT   32256        // = 512*63 = 1008*32 = 252*128
#define BNb  1008
#define KSPLIT 21         // head GEMM split-K slices (8064 = 21*384)

typedef __nv_bfloat16 bf16;

// ---- static device scratch ----
__device__ float g_y[9][(size_t)TT * Dd];
__device__ float g_xn[(size_t)BMr * Ll];
__device__ float g_mean[BMr];
__device__ float g_std[BMr];
__device__ float g_tokin[(size_t)TT * Dd];
__device__ float g_xz[(size_t)TT * 1024];      // up to 2 roles x (xi|z)
__device__ float g_tmp[(size_t)TT * Dd];
__device__ float g_chout[(size_t)TT * Dd];
__device__ float g_headp[(size_t)KSPLIT * BMr * PREDp];

// bf16 hi/lo activation buffers (GEMM A operands)
__device__ bf16 g_nh[(size_t)TT * Dd],  g_nl[(size_t)TT * Dd];    // norm / head-A (same size)
__device__ bf16 g_ch[(size_t)TT * Dd],  g_cl[(size_t)TT * Dd];    // chr
__device__ bf16 g_ysh[(size_t)TT * 512], g_ysl[(size_t)TT * 512]; // scan outputs

// bf16 hi/lo weight buffers (GEMM B operands)
__device__ bf16 g_inwh[4 * 3 * 512 * 128], g_inwl[4 * 3 * 512 * 128];
__device__ bf16 g_outwh[4 * 3 * 128 * 256], g_outwl[4 * 3 * 128 * 256];
__device__ bf16 g_wph[4 * 128 * 512], g_wpl[4 * 128 * 512];
__device__ bf16 g_hdh[96 * 8064], g_hdl[96 * 8064];

__device__ __forceinline__ void bsplit(float v, bf16& h, bf16& l) {
    h = __float2bfloat16(v);
    l = __float2bfloat16(v - __bfloat162float(h));
}

// ======================= weight pre-split kernels =======================
__global__ void k_wsplit(const float* __restrict__ w, bf16* __restrict__ h,
                         bf16* __restrict__ l, int n) {
    for (int i = blockIdx.x * 256 + threadIdx.x; i < n; i += gridDim.x * 256)
        bsplit(w[i], h[i], l[i]);
}

// channel out_proj pack+split: wp[l][d][k<256]=outw[l,1][d][k]; wp[l][d][256+k]=outw[l,2][d][k]
__global__ void k_packsplit(const float* __restrict__ outw, bf16* __restrict__ h,
                            bf16* __restrict__ l) {
    int idx = blockIdx.x * 256 + threadIdx.x;
    if (idx >= 4 * 128 * 256) return;
    int lyr = idx >> 15, rem = idx & 32767;
    int d = rem >> 8, k = rem & 255;
    float w1 = outw[(size_t)(lyr * 3 + 1) * 32768 + d * 256 + k];
    float w2 = outw[(size_t)(lyr * 3 + 2) * 32768 + d * 256 + k];
    size_t o = (size_t)lyr * 65536 + d * 512 + k;
    bsplit(w1, h[o], l[o]);
    bsplit(w2, h[o + 256], l[o + 256]);
}

// ======================= warp-mma bf16-split GEMM =======================
// C[M,NT] = A[M,K] @ Bw[NT,K]^T, pre-split bf16 hi/lo operands, 3 HMMA terms.
// grid = (ceil(NT/64), M/128, nsplit), block = 256. flags: 1 += C, 2 += R.

#define SASTR 40   // smem row stride (bf16): 80B -> conflict-free ldmatrix

__device__ __forceinline__ uint32_t smem_u32(const void* p) {
    return (uint32_t)__cvta_generic_to_shared(p);
}

__device__ __forceinline__ void mma16816(float* d, const uint32_t* a, const uint32_t* b) {
    asm volatile(
        "mma.sync.aligned.m16n8k16.row.col.f32.bf16.bf16.f32 "
        "{%0,%1,%2,%3},{%4,%5,%6,%7},{%8,%9},{%0,%1,%2,%3};"
        : "+f"(d[0]), "+f"(d[1]), "+f"(d[2]), "+f"(d[3])
        : "r"(a[0]), "r"(a[1]), "r"(a[2]), "r"(a[3]), "r"(b[0]), "r"(b[1]));
}

__device__ __forceinline__ void ldm_x4(uint32_t* r, uint32_t a) {
    asm volatile("ldmatrix.sync.aligned.m8n8.x4.shared.b16 {%0,%1,%2,%3}, [%4];"
                 : "=r"(r[0]), "=r"(r[1]), "=r"(r[2]), "=r"(r[3]) : "r"(a));
}

template <int NT>
__global__ __launch_bounds__(256) void k_mma(const bf16* __restrict__ Ah,
                                             const bf16* __restrict__ Al,
                                             const bf16* __restrict__ Bh,
                                             const bf16* __restrict__ Bl,
                                             float* __restrict__ C,
                                             const float* __restrict__ R,
                                             int K, int klen, int flags) {
    __shared__ bf16 sA[2][128 * SASTR];
    __shared__ bf16 sB[2][64 * SASTR];

    int tid = threadIdx.x;
    int warp = tid >> 5, lane = tid & 31;
    int gq = lane >> 2, tig = lane & 3;
    int warpM = warp >> 1, warpN = warp & 1;
    int m0 = blockIdx.y * 128;
    int n0 = blockIdx.x * 64;
    int kbeg = blockIdx.z * klen;
    C += (size_t)blockIdx.z * ((size_t)gridDim.y * 128) * NT;

    // copy mappings (conflict-free phases: consecutive threads -> consecutive rows)
    int arow = tid & 127, ac = (tid >> 7) << 4;   // A: 128 rows x 32 cols, 2 x uint4
    int brow = tid & 63,  bc = (tid >> 6) << 3;   // B: 64 rows x 32 cols, 1 x uint4
    bool bvalid = ((NT & 63) == 0) || (n0 + brow < NT);

    // ldmatrix per-thread source offsets
    int g = lane >> 3, rr = lane & 7;
    int aoff = (warpM * 32 + (g & 1) * 8 + rr) * SASTR + (g >> 1) * 8;
    int boff = (warpN * 32 + (g >> 1) * 8 + rr) * SASTR + (g & 1) * 8;
    uint32_t sA0 = smem_u32(&sA[0][0]), sA1 = smem_u32(&sA[1][0]);
    uint32_t sB0 = smem_u32(&sB[0][0]), sB1 = smem_u32(&sB[1][0]);

    float acc[2][4][4];
#pragma unroll
    for (int i = 0; i < 2; ++i)
#pragma unroll
        for (int j = 0; j < 4; ++j)
#pragma unroll
            for (int r = 0; r < 4; ++r) acc[i][j][r] = 0.f;

    uint4 rAh[2], rAl[2], rBh, rBl;
    auto ldAB = [&](int k0) {
        size_t ao = (size_t)(m0 + arow) * K + k0 + ac;
        rAh[0] = *reinterpret_cast<const uint4*>(Ah + ao);
        rAh[1] = *reinterpret_cast<const uint4*>(Ah + ao + 8);
        rAl[0] = *reinterpret_cast<const uint4*>(Al + ao);
        rAl[1] = *reinterpret_cast<const uint4*>(Al + ao + 8);
        if (bvalid) {
            size_t bo = (size_t)(n0 + brow) * K + k0 + bc;
            rBh = *reinterpret_cast<const uint4*>(Bh + bo);
            rBl = *reinterpret_cast<const uint4*>(Bl + bo);
        } else {
            rBh = make_uint4(0, 0, 0, 0);
            rBl = make_uint4(0, 0, 0, 0);
        }
    };

    ldAB(kbeg);
    int nch = klen >> 5;
    for (int ch = 0; ch < nch; ++ch) {
        *reinterpret_cast<uint4*>(&sA[0][arow * SASTR + ac])     = rAh[0];
        *reinterpret_cast<uint4*>(&sA[0][arow * SASTR + ac + 8]) = rAh[1];
        *reinterpret_cast<uint4*>(&sA[1][arow * SASTR + ac])     = rAl[0];
        *reinterpret_cast<uint4*>(&sA[1][arow * SASTR + ac + 8]) = rAl[1];
        *reinterpret_cast<uint4*>(&sB[0][brow * SASTR + bc]) = rBh;
        *reinterpret_cast<uint4*>(&sB[1][brow * SASTR + bc]) = rBl;
        __syncthreads();
        if (ch + 1 < nch) ldAB(kbeg + ((ch + 1) << 5));

#pragma unroll
        for (int kk = 0; kk < 2; ++kk) {
            int kb = kk * 16;
            uint32_t ah[2][4], al[2][4];
            ldm_x4(ah[0], sA0 + (uint32_t)(aoff + kb) * 2);
            ldm_x4(ah[1], sA0 + (uint32_t)(aoff + 16 * SASTR + kb) * 2);
            ldm_x4(al[0], sA1 + (uint32_t)(aoff + kb) * 2);
            ldm_x4(al[1], sA1 + (uint32_t)(aoff + 16 * SASTR + kb) * 2);
            uint32_t bh[4][2], bl[4][2], t0[4], t1[4];
            ldm_x4(t0, sB0 + (uint32_t)(boff + kb) * 2);
            ldm_x4(t1, sB0 + (uint32_t)(boff + 16 * SASTR + kb) * 2);
            bh[0][0] = t0[0]; bh[0][1] = t0[1]; bh[1][0] = t0[2]; bh[1][1] = t0[3];
            bh[2][0] = t1[0]; bh[2][1] = t1[1]; bh[3][0] = t1[2]; bh[3][1] = t1[3];
            ldm_x4(t0, sB1 + (uint32_t)(boff + kb) * 2);
            ldm_x4(t1, sB1 + (uint32_t)(boff + 16 * SASTR + kb) * 2);
            bl[0][0] = t0[0]; bl[0][1] = t0[1]; bl[1][0] = t0[2]; bl[1][1] = t0[3];
            bl[2][0] = t1[0]; bl[2][1] = t1[1]; bl[3][0] = t1[2]; bl[3][1] = t1[3];
#pragma unroll
            for (int i = 0; i < 2; ++i)
#pragma unroll
                for (int j = 0; j < 4; ++j) {
                    mma16816(acc[i][j], ah[i], bh[j]);
                    mma16816(acc[i][j], ah[i], bl[j]);
                    mma16816(acc[i][j], al[i], bh[j]);
                }
        }
        __syncthreads();
    }

#pragma unroll
    for (int i = 0; i < 2; ++i) {
        int grow = m0 + warpM * 32 + i * 16 + gq;
#pragma unroll
        for (int j = 0; j < 4; ++j) {
            int gcol = n0 + warpN * 32 + j * 8 + 2 * tig;
            if ((NT & 63) != 0 && gcol >= NT) continue;
            size_t o0 = (size_t)grow * NT + gcol;
            size_t o1 = (size_t)(grow + 8) * NT + gcol;
            float2 v0 = make_float2(acc[i][j][0], acc[i][j][1]);
            float2 v1 = make_float2(acc[i][j][2], acc[i][j][3]);
            if (flags & 2) {
                float2 t0 = *reinterpret_cast<const float2*>(R + o0);
                float2 t1 = *reinterpret_cast<const float2*>(R + o1);
                v0.x += t0.x; v0.y += t0.y; v1.x += t1.x; v1.y += t1.y;
            }
            if (flags & 1) {
                float2 t0 = *reinterpret_cast<const float2*>(C + o0);
                float2 t1 = *reinterpret_cast<const float2*>(C + o1);
                v0.x += t0.x; v0.y += t0.y; v1.x += t1.x; v1.y += t1.y;
            }
            *reinterpret_cast<float2*>(C + o0) = v0;
            *reinterpret_cast<float2*>(C + o1) = v1;
        }
    }
}

// ======================= fused conv+x_proj+dt+scan (multi-role) =======================
__global__ __launch_bounds__(256) void k_fscan(
    const float* __restrict__ xz, int xzs,
    const float* __restrict__ xw, const float* __restrict__ dtw,
    const float* __restrict__ dtb, const float* __restrict__ cw,
    const float* __restrict__ cb, const float* __restrict__ alog,
    const float* __restrict__ dssm,
    bf16* __restrict__ yh, bf16* __restrict__ yl, int ystr, int slen) {
    __shared__ float sW[40 * DIi];
    __shared__ float su[DIi];
    __shared__ float sx[40];

    int r = blockIdx.y;
    int rev = r;
    xz  += (size_t)r * 512;
    xw  += (size_t)r * 40 * DIi;
    dtw += (size_t)r * DIi * DTRr;
    dtb += (size_t)r * DIi;
    cw  += (size_t)r * DIi * DCc;
    cb  += (size_t)r * DIi;
    alog += (size_t)r * DIi * NSTn;
    dssm += (size_t)r * DIi;
    yh  += (size_t)r * 256;
    yl  += (size_t)r * 256;

    int c = threadIdx.x;
    int warp = c >> 5, lane = c & 31;
    int b = blockIdx.x;

    for (int i = c; i < 40 * DIi; i += 256) sW[i] = xw[i];

    float dtwr[DTRr];
#pragma unroll
    for (int q = 0; q < DTRr; ++q) dtwr[q] = dtw[c * DTRr + q];
    float dtbr = dtb[c];
    float cw0 = cw[c * 4 + 0], cw1 = cw[c * 4 + 1], cw2 = cw[c * 4 + 2], cw3 = cw[c * 4 + 3];
    float cbr = cb[c];
    float dss = dssm[c];

    float a[NSTn];
#pragma unroll
    for (int n = 0; n < NSTn; ++n) a[n] = -__expf(alog[c * NSTn + n]);
    float a0 = a[0];
    bool geom = true;
#pragma unroll
    for (int n = 1; n < NSTn; ++n)
        geom = geom && (fabsf(a[n] - (float)(n + 1) * a0) <= 1e-4f * fabsf(a[n]));
    float h[NSTn];
#pragma unroll
    for (int n = 0; n < NSTn; ++n) h[n] = 0.f;

    __syncthreads();

    size_t base = (size_t)b * slen;
    int s0 = rev ? slen - 1 : 0;
    float xi_nx = xz[(base + s0) * xzs + c];
    float z_nx  = xz[(base + s0) * xzs + DIi + c];
    float r0 = 0.f, r1 = 0.f, r2 = 0.f, r3 = 0.f;

    for (int step = 0; step < slen; ++step) {
        int s = rev ? slen - 1 - step : step;
        r0 = r1; r1 = r2; r2 = r3; r3 = xi_nx;
        float zv = z_nx;
        if (step + 1 < slen) {
            int sn = rev ? s - 1 : s + 1;
            xi_nx = xz[(base + sn) * xzs + c];
            z_nx  = xz[(base + sn) * xzs + DIi + c];
        }
        float acc = fmaf(cw0, r0, fmaf(cw1, r1, fmaf(cw2, r2, fmaf(cw3, r3, cbr))));
        float uv = acc / (1.f + __expf(-acc));
        su[c] = uv;
        __syncthreads();
#pragma unroll
        for (int oo = 0; oo < 5; ++oo) {
            int o = warp * 5 + oo;
            const float* wr = &sW[o * DIi];
            float p = 0.f;
#pragma unroll
            for (int k8 = 0; k8 < 8; ++k8)
                p = fmaf(su[lane + 32 * k8], wr[lane + 32 * k8], p);
#pragma unroll
            for (int off = 16; off; off >>= 1) p += __shfl_xor_sync(0xffffffffu, p, off);
            if (lane == 0) sx[o] = p;
        }
        __syncthreads();
        float dtacc = dtbr;
#pragma unroll
        for (int q = 0; q < DTRr; ++q) dtacc = fmaf(sx[q], dtwr[q], dtacc);
        float dtv = (dtacc > 20.f) ? dtacc : __logf(1.f + __expf(dtacc));
        float du = dtv * uv;
        float ysum = 0.f;
        if (geom) {
            float w = __expf(dtv * a0);
            float e = 1.f;
#pragma unroll
            for (int n = 0; n < NSTn; ++n) {
                e *= w;
                h[n] = fmaf(h[n], e, du * sx[8 + n]);
                ysum = fmaf(h[n], sx[24 + n], ysum);
            }
        } else {
#pragma unroll
            for (int n = 0; n < NSTn; ++n) {
                float e = __expf(dtv * a[n]);
                h[n] = fmaf(h[n], e, du * sx[8 + n]);
                ysum = fmaf(h[n], sx[24 + n], ysum);
            }
        }
        float sg = 1.f / (1.f + __expf(-zv));
        float yv = (ysum + uv * dss) * (zv * sg);
        size_t yo = (base + s) * ystr + c;
        bsplit(yv, yh[yo], yl[yo]);
    }
}

// ======================= fused combine + LN (+transpose), bf16-split out ==========
struct P5 { const float* p[5]; };

template <int TRANS>
__global__ void k_combineln(P5 pa, int na, const float* __restrict__ ra,
                            P5 pb, int nb, const float* __restrict__ rb,
                            const float* __restrict__ w, const float* __restrict__ bia,
                            float* __restrict__ comb,
                            bf16* __restrict__ nh, bf16* __restrict__ nl) {
    __shared__ float ca[5], cb2[5];
    if (threadIdx.x == 0) {
        float mx = -1e30f;
        for (int i = 0; i < na; ++i) mx = fmaxf(mx, ra[i]);
        float s = 0.f;
        for (int i = 0; i < na; ++i) { ca[i] = __expf(ra[i] - mx); s += ca[i]; }
        for (int i = 0; i < na; ++i) ca[i] /= s;
        mx = -1e30f;
        for (int i = 0; i < nb; ++i) mx = fmaxf(mx, rb[i]);
        s = 0.f;
        for (int i = 0; i < nb; ++i) { cb2[i] = __expf(rb[i] - mx); s += cb2[i]; }
        for (int i = 0; i < nb; ++i) cb2[i] /= s;
    }
    __syncthreads();
    int warp = threadIdx.x >> 5, lane = threadIdx.x & 31;
    int row = blockIdx.x * 4 + warp;
    if (row >= TT) return;
    int irow = row;
    if (TRANS) {
        int m = row & 31;
        int bn = row >> 5;
        int n = bn % Nn, b = bn / Nn;
        irow = (b * Mm + m) * Nn + n;
    }
    float v[4];
#pragma unroll
    for (int q = 0; q < 4; ++q) {
        size_t off = (size_t)irow * Dd + lane + 32 * q;
        float acc = 0.f;
        for (int j = 0; j < na; ++j) acc = fmaf(ca[j], pa.p[j][off], acc);
        for (int j = 0; j < nb; ++j) acc = fmaf(cb2[j], pb.p[j][off], acc);
        v[q] = acc;
        comb[off] = acc;
    }
    float s = v[0] + v[1] + v[2] + v[3];
#pragma unroll
    for (int o = 16; o; o >>= 1) s += __shfl_xor_sync(0xffffffffu, s, o);
    float mu = s * (1.f / Dd);
    float q0 = 0.f;
#pragma unroll
    for (int q = 0; q < 4; ++q) { v[q] -= mu; q0 += v[q] * v[q]; }
#pragma unroll
    for (int o = 16; o; o >>= 1) q0 += __shfl_xor_sync(0xffffffffu, q0, o);
    float r = rsqrtf(q0 * (1.f / Dd) + 1e-5f);
    size_t ob = (size_t)row * Dd;
#pragma unroll
    for (int q = 0; q < 4; ++q) {
        int e = lane + 32 * q;
        bsplit(v[q] * r * w[e] + bia[e], nh[ob + e], nl[ob + e]);
    }
}

// ======================= other supporting kernels =======================

__global__ void k_stats(const float* __restrict__ x, float* __restrict__ mean,
                        float* __restrict__ stdv, float* __restrict__ xn) {
    int bm = blockIdx.x;
    int b = bm >> 5, m = bm & 31;
    int tid = threadIdx.x;
    float s = 0.f, sq = 0.f;
    for (int l = tid; l < Ll; l += 256) {
        float v = x[((size_t)b * Ll + l) * Mm + m];
        s += v; sq += v * v;
    }
    __shared__ float sh1[256], sh2[256];
    sh1[tid] = s; sh2[tid] = sq;
    __syncthreads();
    for (int o = 128; o; o >>= 1) {
        if (tid < o) { sh1[tid] += sh1[tid + o]; sh2[tid] += sh2[tid + o]; }
        __syncthreads();
    }
    __shared__ float smu, ssd;
    if (tid == 0) {
        float mu = sh1[0] / (float)Ll;
        float var = (sh2[0] - (float)Ll * mu * mu) / (float)(Ll - 1);
        if (var < 0.f) var = 0.f;
        float sd = sqrtf(var) + 1e-5f;
        smu = mu; ssd = sd;
        mean[bm] = mu; stdv[bm] = sd;
    }
    __syncthreads();
    float inv = 1.f / ssd;
    float mu = smu;
    for (int l = tid; l < Ll; l += 256) {
        xn[(size_t)bm * Ll + l] = (x[((size_t)b * Ll + l) * Mm + m] - mu) * inv;
    }
}

__global__ void k_patch(const float* __restrict__ xn, const float* __restrict__ pw,
                        const float* __restrict__ pb, const float* __restrict__ pos,
                        float* __restrict__ h) {
    int blk = blockIdx.x;
    int n = blk % Nn, bm = blk / Nn;
    int d = threadIdx.x;
    __shared__ float xs[Pp];
    if (d < Pp) xs[d] = xn[(size_t)bm * Ll + n * Sss + d];
    __syncthreads();
    float acc = pb[d];
#pragma unroll
    for (int p = 0; p < Pp; ++p) acc = fmaf(xs[p], pw[d * Pp + p], acc);
    acc += pos[n * Dd + d];
    h[(size_t)blk * Dd + d] = acc;
}

__global__ void k_ln(const float* __restrict__ x, const float* __restrict__ w,
                     const float* __restrict__ bia, float* __restrict__ out, int rows) {
    int warp = threadIdx.x >> 5, lane = threadIdx.x & 31;
    int row = blockIdx.x * 4 + warp;
    if (row >= rows) return;
    const float* xr = x + (size_t)row * Dd;
    float v0 = xr[lane], v1 = xr[lane + 32], v2 = xr[lane + 64], v3 = xr[lane + 96];
    float s = v0 + v1 + v2 + v3;
#pragma unroll
    for (int o = 16; o; o >>= 1) s += __shfl_xor_sync(0xffffffffu, s, o);
    float mu = s * (1.f / Dd);
    float d0 = v0 - mu, d1 = v1 - mu, d2 = v2 - mu, d3 = v3 - mu;
    float q = d0 * d0 + d1 * d1 + d2 * d2 + d3 * d3;
#pragma unroll
    for (int o = 16; o; o >>= 1) q += __shfl_xor_sync(0xffffffffu, q, o);
    float r = rsqrtf(q * (1.f / Dd) + 1e-5f);
    float* orow = out + (size_t)row * Dd;
    orow[lane]      = d0 * r * w[lane]      + bia[lane];
    orow[lane + 32] = d1 * r * w[lane + 32] + bia[lane + 32];
    orow[lane + 64] = d2 * r * w[lane + 64] + bia[lane + 64];
    orow[lane + 96] = d3 * r * w[lane + 96] + bia[lane + 96];
}

__global__ void k_transback(const float* __restrict__ chout, const float* __restrict__ chin,
                            float* __restrict__ out) {
    size_t total = (size_t)TT * Dd;
    for (size_t i = (size_t)blockIdx.x * blockDim.x + threadIdx.x; i < total;
         i += (size_t)gridDim.x * blockDim.x) {
        int d = (int)(i & 127);
        size_t rest = i >> 7;
        int n = (int)(rest % Nn);
        int bm = (int)(rest / Nn);
        int m = bm & 31, b = bm >> 5;
        size_t src = (((size_t)(b * Nn + n) * Mm + m) << 7) + d;
        out[i] = chout[src] + chin[i];
    }
}

// Norm2D second LN over N, bf16-split output (feeds head GEMM)
__global__ void k_ln_n(const float* __restrict__ x, const float* __restrict__ w2,
                       const float* __restrict__ b2,
                       bf16* __restrict__ oh, bf16* __restrict__ ol) {
    int idx = blockIdx.x * 256 + threadIdx.x;
    if (idx >= BMr * Dd) return;
    int d = idx & 127, bm = idx >> 7;
    const float* base = x + (size_t)bm * Nn * Dd + d;
    float s = 0.f, q = 0.f;
    for (int n = 0; n < Nn; ++n) { float v = base[(size_t)n * Dd]; s += v; q += v * v; }
    float mu = s * (1.f / Nn);
    float var = q * (1.f / Nn) - mu * mu;
    if (var < 0.f) var = 0.f;
    float r = rsqrtf(var + 1e-5f);
    size_t ob = (size_t)bm * Nn * Dd + d;
    for (int n = 0; n < Nn; ++n) {
        float v = (base[(size_t)n * Dd] - mu) * r * w2[n] + b2[n];
        bsplit(v, oh[ob + (size_t)n * Dd], ol[ob + (size_t)n * Dd]);
    }
}

__global__ void k_headred(const float* __restrict__ hp, const float* __restrict__ hb,
                          const float* __restrict__ mean, const float* __restrict__ stdv,
                          float* __restrict__ out) {
    int idx = blockIdx.x * 256 + threadIdx.x;
    if (idx >= Bb * PREDp * Mm) return;
    int m = idx % Mm;
    int p = (idx / Mm) % PREDp;
    int b = idx / (Mm * PREDp);
    int bm = b * Mm + m;
    float s = 0.f;
#pragma unroll 3
    for (int z = 0; z < KSPLIT; ++z)
        s += hp[(size_t)z * BMr * PREDp + (size_t)bm * PREDp + p];
    out[idx] = (s + hb[p]) * stdv[bm] + mean[bm];
}

// ======================= host orchestration =======================

extern "C" void kernel_launch(void* const* d_in, const int* in_sizes, int n_in,
                              void* d_out, int out_size) {
    (void)in_sizes; (void)n_in; (void)out_size;
    const float* x      = (const float*)d_in[0];
    const float* patchw = (const float*)d_in[1];
    const float* patchb = (const float*)d_in[2];
    const float* pos    = (const float*)d_in[3];
    const float* alpha  = (const float*)d_in[4];
    const float* beta   = (const float*)d_in[5];
    const float* theta  = (const float*)d_in[6];
    const float* gma    = (const float*)d_in[7];
    const float* tnw    = (const float*)d_in[8];
    const float* tnb    = (const float*)d_in[9];
    const float* cnw    = (const float*)d_in[10];
    const float* cnb    = (const float*)d_in[11];
    const float* inw    = (const float*)d_in[12];
    const float* cvw    = (const float*)d_in[13];
    const float* cvb    = (const float*)d_in[14];
    const float* xpw    = (const float*)d_in[15];
    const float* dtw    = (const float*)d_in[16];
    const float* dtbv   = (const float*)d_in[17];
    const float* alog   = (const float*)d_in[18];
    const float* dssm   = (const float*)d_in[19];
    const float* outw   = (const float*)d_in[20];
    const float* n2w1   = (const float*)d_in[21];
    const float* n2b1   = (const float*)d_in[22];
    const float* n2w2   = (const float*)d_in[23];
    const float* n2b2   = (const float*)d_in[24];
    const float* headw  = (const float*)d_in[25];
    const float* headb  = (const float*)d_in[26];

    float *p_y, *p_xn, *p_mean, *p_std, *p_tokin, *p_xz, *p_tmp, *p_chout, *p_headp;
    bf16 *p_nh, *p_nl, *p_ch, *p_cl, *p_ysh, *p_ysl;
    bf16 *p_inwh, *p_inwl, *p_outwh, *p_outwl, *p_wph, *p_wpl, *p_hdh, *p_hdl;
    cudaGetSymbolAddress((void**)&p_y,     g_y);
    cudaGetSymbolAddress((void**)&p_xn,    g_xn);
    cudaGetSymbolAddress((void**)&p_mean,  g_mean);
    cudaGetSymbolAddress((void**)&p_std,   g_std);
    cudaGetSymbolAddress((void**)&p_tokin, g_tokin);
    cudaGetSymbolAddress((void**)&p_xz,    g_xz);
    cudaGetSymbolAddress((void**)&p_tmp,   g_tmp);
    cudaGetSymbolAddress((void**)&p_chout, g_chout);
    cudaGetSymbolAddress((void**)&p_headp, g_headp);
    cudaGetSymbolAddress((void**)&p_nh,    g_nh);
    cudaGetSymbolAddress((void**)&p_nl,    g_nl);
    cudaGetSymbolAddress((void**)&p_ch,    g_ch);
    cudaGetSymbolAddress((void**)&p_cl,    g_cl);
    cudaGetSymbolAddress((void**)&p_ysh,   g_ysh);
    cudaGetSymbolAddress((void**)&p_ysl,   g_ysl);
    cudaGetSymbolAddress((void**)&p_inwh,  g_inwh);
    cudaGetSymbolAddress((void**)&p_inwl,  g_inwl);
    cudaGetSymbolAddress((void**)&p_outwh, g_outwh);
    cudaGetSymbolAddress((void**)&p_outwl, g_outwl);
    cudaGetSymbolAddress((void**)&p_wph,   g_wph);
    cudaGetSymbolAddress((void**)&p_wpl,   g_wpl);
    cudaGetSymbolAddress((void**)&p_hdh,   g_hdh);
    cudaGetSymbolAddress((void**)&p_hdl,   g_hdl);

    float* yT[5]; float* yC[5];
    yT[0] = p_y; yC[0] = p_y;
    for (int i = 1; i <= 4; ++i) {
        yT[i] = p_y + (size_t)i * TT * Dd;
        yC[i] = p_y + (size_t)(4 + i) * TT * Dd;
    }

    // one-time weight pre-split (deterministic; runs every call)
    k_wsplit<<<768, 256>>>(inw, p_inwh, p_inwl, 4 * 3 * 512 * 128);
    k_wsplit<<<384, 256>>>(outw, p_outwh, p_outwl, 4 * 3 * 128 * 256);
    k_packsplit<<<512, 256>>>(outw, p_wph, p_wpl);
    k_wsplit<<<756, 256>>>(headw, p_hdh, p_hdl, 96 * 8064);

    k_stats<<<BMr, 256>>>(x, p_mean, p_std, p_xn);
    k_patch<<<TT, Dd>>>(p_xn, patchw, patchb, pos, p_y);

    const int GY = TT / 128;   // 252

    for (int l = 0; l < NLl; ++l) {
        // ---- token mixing ----
        P5 pa = {}, pb = {};
        for (int i = 0; i <= l; ++i) { pa.p[i] = yT[i]; pb.p[i] = yC[i]; }
        k_combineln<0><<<TT / 4, 128>>>(pa, l + 1, alpha + l * NLl,
                                        pb, l + 1, beta + l * NLl,
                                        tnw + l * Dd, tnb + l * Dd, p_tokin, p_nh, p_nl);
        {
            size_t lr = (size_t)(l * 3 + 0);
            k_mma<512><<<dim3(8, GY, 1), 256>>>(p_nh, p_nl,
                                                p_inwh + lr * 65536, p_inwl + lr * 65536,
                                                p_xz, nullptr, 128, 128, 0);
            k_fscan<<<dim3(BMr, 1), 256>>>(p_xz, 512,
                                           xpw + lr * 40 * DIi, dtw + lr * DIi * DTRr,
                                           dtbv + lr * DIi, cvw + lr * DIi * DCc,
                                           cvb + lr * DIi, alog + lr * DIi * NSTn,
                                           dssm + lr * DIi, p_ysh, p_ysl, 256, Nn);
            k_mma<128><<<dim3(2, GY, 1), 256>>>(p_ysh, p_ysl,
                                                p_outwh + lr * 32768, p_outwl + lr * 32768,
                                                yT[l + 1], p_tokin, 256, 256, 2);
        }

        // ---- channel mixing (fwd+bwd fused) ----
        P5 pc = {}, pd = {};
        for (int i = 0; i <= l + 1; ++i) pc.p[i] = yT[i];
        for (int i = 0; i <= l; ++i)     pd.p[i] = yC[i];
        k_combineln<1><<<TT / 4, 128>>>(pc, l + 2, theta + l * (NLl + 1),
                                        pd, l + 1, gma + l * NLl,
                                        cnw + l * Dd, cnb + l * Dd, p_tokin, p_ch, p_cl);
        {
            size_t lr = (size_t)(l * 3 + 1);
            k_mma<1024><<<dim3(16, GY, 1), 256>>>(p_ch, p_cl,
                                                  p_inwh + lr * 65536, p_inwl + lr * 65536,
                                                  p_xz, nullptr, 128, 128, 0);
            k_fscan<<<dim3(BNb, 2), 256>>>(p_xz, 1024,
                                           xpw + lr * 40 * DIi, dtw + lr * DIi * DTRr,
                                           dtbv + lr * DIi, cvw + lr * DIi * DCc,
                                           cvb + lr * DIi, alog + lr * DIi * NSTn,
                                           dssm + lr * DIi, p_ysh, p_ysl, 512, Mm);
            k_mma<128><<<dim3(2, GY, 1), 256>>>(p_ysh, p_ysl,
                                                p_wph + (size_t)l * 65536, p_wpl + (size_t)l * 65536,
                                                p_chout, nullptr, 512, 512, 0);
        }
        k_transback<<<4096, 256>>>(p_chout, p_tokin, yC[l + 1]);
    }

    k_ln<<<TT / 4, 128>>>(yC[4], n2w1, n2b1, p_tmp, TT);
    k_ln_n<<<(BMr * Dd + 255) / 256, 256>>>(p_tmp, n2w2, n2b2, p_nh, p_nl);
    k_mma<96><<<dim3(2, 4, KSPLIT), 256>>>(p_nh, p_nl, p_hdh, p_hdl,
                                           p_headp, nullptr, 8064, 384, 0);
    k_headred<<<(Bb * PREDp * Mm + 255) / 256, 256>>>(p_headp, headb, p_mean, p_std,
                                                      (float*)d_out);
}

// round 7
// speedup vs baseline: 1.1309x; 1.1309x over previous
#include <cuda_runtime.h>
#include <cuda_bf16.h>
#include <math.h>
#include <stdint.h>

// ---- problem dims ----
#define Bb   16
#define Ll   512
#define Mm   32
#define PREDp 96
#define Pp   16
#define Sss  8
#define Dd   128
#define NSTn 16
#define DCc  4
#define NLl  4
#define Nn   63
#define DIi  256
#define DTRr 8
#define BMr  512
#define TT   32256        // = 512*63 = 1008*32 = 252*128
#define BNb  1008
#define KSPLIT 21         // head GEMM split-K slices (8064 = 21*384)

typedef __nv_bfloat16 bf16;

// ---- static device scratch ----
__device__ float g_y[9][(size_t)TT * Dd];
__device__ float g_xn[(size_t)BMr * Ll];
__device__ float g_mean[BMr];
__device__ float g_std[BMr];
__device__ float g_tokin[(size_t)TT * Dd];
__device__ float g_xz[(size_t)TT * 1024];      // up to 2 roles x (xi|z)
__device__ float g_tmp[(size_t)TT * Dd];
__device__ float g_chout[(size_t)TT * Dd];
__device__ float g_headp[(size_t)KSPLIT * BMr * PREDp];

// bf16 hi/lo activation buffers (GEMM A operands)
__device__ bf16 g_nh[(size_t)TT * Dd],  g_nl[(size_t)TT * Dd];    // norm / head-A
__device__ bf16 g_ch[(size_t)TT * Dd],  g_cl[(size_t)TT * Dd];    // chr
__device__ bf16 g_ysh[(size_t)TT * 512], g_ysl[(size_t)TT * 512]; // scan outputs

// bf16 hi/lo weight buffers (GEMM B operands)
__device__ bf16 g_inwh[4 * 3 * 512 * 128], g_inwl[4 * 3 * 512 * 128];
__device__ bf16 g_outwh[4 * 3 * 128 * 256], g_outwl[4 * 3 * 128 * 256];
__device__ bf16 g_wph[4 * 128 * 512], g_wpl[4 * 128 * 512];
__device__ bf16 g_hdh[96 * 8064], g_hdl[96 * 8064];

__device__ __forceinline__ void bsplit(float v, bf16& h, bf16& l) {
    h = __float2bfloat16(v);
    l = __float2bfloat16(v - __bfloat162float(h));
}

// ======================= weight pre-split kernels =======================
__global__ void k_wsplit(const float* __restrict__ w, bf16* __restrict__ h,
                         bf16* __restrict__ l, int n) {
    for (int i = blockIdx.x * 256 + threadIdx.x; i < n; i += gridDim.x * 256)
        bsplit(w[i], h[i], l[i]);
}

__global__ void k_packsplit(const float* __restrict__ outw, bf16* __restrict__ h,
                            bf16* __restrict__ l) {
    int idx = blockIdx.x * 256 + threadIdx.x;
    if (idx >= 4 * 128 * 256) return;
    int lyr = idx >> 15, rem = idx & 32767;
    int d = rem >> 8, k = rem & 255;
    float w1 = outw[(size_t)(lyr * 3 + 1) * 32768 + d * 256 + k];
    float w2 = outw[(size_t)(lyr * 3 + 2) * 32768 + d * 256 + k];
    size_t o = (size_t)lyr * 65536 + d * 512 + k;
    bsplit(w1, h[o], l[o]);
    bsplit(w2, h[o + 256], l[o + 256]);
}

// ======================= warp-mma bf16-split GEMM =======================
// C[M,NT] = A[M,K] @ Bw[NT,K]^T, pre-split bf16 hi/lo operands, 3 HMMA terms.
// grid = (ceil(NT/64), M/128, nsplit), block = 256. flags: 1 += C, 2 += R.

#define SASTR 40   // smem row stride (bf16): 80B -> conflict-free ldmatrix

__device__ __forceinline__ uint32_t smem_u32(const void* p) {
    return (uint32_t)__cvta_generic_to_shared(p);
}

__device__ __forceinline__ void mma16816(float* d, const uint32_t* a, const uint32_t* b) {
    asm volatile(
        "mma.sync.aligned.m16n8k16.row.col.f32.bf16.bf16.f32 "
        "{%0,%1,%2,%3},{%4,%5,%6,%7},{%8,%9},{%0,%1,%2,%3};"
        : "+f"(d[0]), "+f"(d[1]), "+f"(d[2]), "+f"(d[3])
        : "r"(a[0]), "r"(a[1]), "r"(a[2]), "r"(a[3]), "r"(b[0]), "r"(b[1]));
}

__device__ __forceinline__ void ldm_x4(uint32_t* r, uint32_t a) {
    asm volatile("ldmatrix.sync.aligned.m8n8.x4.shared.b16 {%0,%1,%2,%3}, [%4];"
                 : "=r"(r[0]), "=r"(r[1]), "=r"(r[2]), "=r"(r[3]) : "r"(a));
}

template <int NT>
__global__ __launch_bounds__(256) void k_mma(const bf16* __restrict__ Ah,
                                             const bf16* __restrict__ Al,
                                             const bf16* __restrict__ Bh,
                                             const bf16* __restrict__ Bl,
                                             float* __restrict__ C,
                                             const float* __restrict__ R,
                                             int K, int klen, int flags) {
    __shared__ bf16 sA[2][128 * SASTR];
    __shared__ bf16 sB[2][64 * SASTR];

    int tid = threadIdx.x;
    int warp = tid >> 5, lane = tid & 31;
    int gq = lane >> 2, tig = lane & 3;
    int warpM = warp >> 1, warpN = warp & 1;
    int m0 = blockIdx.y * 128;
    int n0 = blockIdx.x * 64;
    int kbeg = blockIdx.z * klen;
    C += (size_t)blockIdx.z * ((size_t)gridDim.y * 128) * NT;

    // coalesced copy mapping: 4 consecutive threads per row (16B each = 64B runs)
    int arow = tid >> 2;              // 0..63 (also covers arow+64)
    int acol = (tid & 3) << 3;        // bf16 elems: 0,8,16,24
    bool bvalid = ((NT & 63) == 0) || (n0 + arow < NT);

    // ldmatrix per-thread source offsets
    int g = lane >> 3, rr = lane & 7;
    int aoff = (warpM * 32 + (g & 1) * 8 + rr) * SASTR + (g >> 1) * 8;
    int boff = (warpN * 32 + (g >> 1) * 8 + rr) * SASTR + (g & 1) * 8;
    uint32_t sA0 = smem_u32(&sA[0][0]), sA1 = smem_u32(&sA[1][0]);
    uint32_t sB0 = smem_u32(&sB[0][0]), sB1 = smem_u32(&sB[1][0]);

    float acc[2][4][4];
#pragma unroll
    for (int i = 0; i < 2; ++i)
#pragma unroll
        for (int j = 0; j < 4; ++j)
#pragma unroll
            for (int r = 0; r < 4; ++r) acc[i][j][r] = 0.f;

    uint4 rAh[2], rAl[2], rBh, rBl;
    auto ldAB = [&](int k0) {
        size_t a0 = (size_t)(m0 + arow) * K + k0 + acol;
        size_t a1 = (size_t)(m0 + arow + 64) * K + k0 + acol;
        rAh[0] = *reinterpret_cast<const uint4*>(Ah + a0);
        rAh[1] = *reinterpret_cast<const uint4*>(Ah + a1);
        rAl[0] = *reinterpret_cast<const uint4*>(Al + a0);
        rAl[1] = *reinterpret_cast<const uint4*>(Al + a1);
        if (bvalid) {
            size_t bo = (size_t)(n0 + arow) * K + k0 + acol;
            rBh = *reinterpret_cast<const uint4*>(Bh + bo);
            rBl = *reinterpret_cast<const uint4*>(Bl + bo);
        } else {
            rBh = make_uint4(0, 0, 0, 0);
            rBl = make_uint4(0, 0, 0, 0);
        }
    };

    ldAB(kbeg);
    int nch = klen >> 5;
    for (int ch = 0; ch < nch; ++ch) {
        *reinterpret_cast<uint4*>(&sA[0][arow * SASTR + acol])        = rAh[0];
        *reinterpret_cast<uint4*>(&sA[0][(arow + 64) * SASTR + acol]) = rAh[1];
        *reinterpret_cast<uint4*>(&sA[1][arow * SASTR + acol])        = rAl[0];
        *reinterpret_cast<uint4*>(&sA[1][(arow + 64) * SASTR + acol]) = rAl[1];
        *reinterpret_cast<uint4*>(&sB[0][arow * SASTR + acol]) = rBh;
        *reinterpret_cast<uint4*>(&sB[1][arow * SASTR + acol]) = rBl;
        __syncthreads();
        if (ch + 1 < nch) ldAB(kbeg + ((ch + 1) << 5));

#pragma unroll
        for (int kk = 0; kk < 2; ++kk) {
            int kb = kk * 16;
            uint32_t ah[2][4], al[2][4];
            ldm_x4(ah[0], sA0 + (uint32_t)(aoff + kb) * 2);
            ldm_x4(ah[1], sA0 + (uint32_t)(aoff + 16 * SASTR + kb) * 2);
            ldm_x4(al[0], sA1 + (uint32_t)(aoff + kb) * 2);
            ldm_x4(al[1], sA1 + (uint32_t)(aoff + 16 * SASTR + kb) * 2);
            uint32_t bh[4][2], bl[4][2], t0[4], t1[4];
            ldm_x4(t0, sB0 + (uint32_t)(boff + kb) * 2);
            ldm_x4(t1, sB0 + (uint32_t)(boff + 16 * SASTR + kb) * 2);
            bh[0][0] = t0[0]; bh[0][1] = t0[1]; bh[1][0] = t0[2]; bh[1][1] = t0[3];
            bh[2][0] = t1[0]; bh[2][1] = t1[1]; bh[3][0] = t1[2]; bh[3][1] = t1[3];
            ldm_x4(t0, sB1 + (uint32_t)(boff + kb) * 2);
            ldm_x4(t1, sB1 + (uint32_t)(boff + 16 * SASTR + kb) * 2);
            bl[0][0] = t0[0]; bl[0][1] = t0[1]; bl[1][0] = t0[2]; bl[1][1] = t0[3];
            bl[2][0] = t1[0]; bl[2][1] = t1[1]; bl[3][0] = t1[2]; bl[3][1] = t1[3];
#pragma unroll
            for (int i = 0; i < 2; ++i)
#pragma unroll
                for (int j = 0; j < 4; ++j) {
                    mma16816(acc[i][j], ah[i], bh[j]);
                    mma16816(acc[i][j], ah[i], bl[j]);
                    mma16816(acc[i][j], al[i], bh[j]);
                }
        }
        __syncthreads();
    }

#pragma unroll
    for (int i = 0; i < 2; ++i) {
        int grow = m0 + warpM * 32 + i * 16 + gq;
#pragma unroll
        for (int j = 0; j < 4; ++j) {
            int gcol = n0 + warpN * 32 + j * 8 + 2 * tig;
            if ((NT & 63) != 0 && gcol >= NT) continue;
            size_t o0 = (size_t)grow * NT + gcol;
            size_t o1 = (size_t)(grow + 8) * NT + gcol;
            float2 v0 = make_float2(acc[i][j][0], acc[i][j][1]);
            float2 v1 = make_float2(acc[i][j][2], acc[i][j][3]);
            if (flags & 2) {
                float2 t0 = *reinterpret_cast<const float2*>(R + o0);
                float2 t1 = *reinterpret_cast<const float2*>(R + o1);
                v0.x += t0.x; v0.y += t0.y; v1.x += t1.x; v1.y += t1.y;
            }
            if (flags & 1) {
                float2 t0 = *reinterpret_cast<const float2*>(C + o0);
                float2 t1 = *reinterpret_cast<const float2*>(C + o1);
                v0.x += t0.x; v0.y += t0.y; v1.x += t1.x; v1.y += t1.y;
            }
            *reinterpret_cast<float2*>(C + o0) = v0;
            *reinterpret_cast<float2*>(C + o1) = v1;
        }
    }
}

// ======================= fused conv+x_proj+dt+scan (multi-role) =======================
__global__ __launch_bounds__(256) void k_fscan(
    const float* __restrict__ xz, int xzs,
    const float* __restrict__ xw, const float* __restrict__ dtw,
    const float* __restrict__ dtb, const float* __restrict__ cw,
    const float* __restrict__ cb, const float* __restrict__ alog,
    const float* __restrict__ dssm,
    bf16* __restrict__ yh, bf16* __restrict__ yl, int ystr, int slen) {
    __shared__ float sW[40 * DIi];
    __shared__ float su[DIi];
    __shared__ float sx[40];

    int r = blockIdx.y;
    int rev = r;
    xz  += (size_t)r * 512;
    xw  += (size_t)r * 40 * DIi;
    dtw += (size_t)r * DIi * DTRr;
    dtb += (size_t)r * DIi;
    cw  += (size_t)r * DIi * DCc;
    cb  += (size_t)r * DIi;
    alog += (size_t)r * DIi * NSTn;
    dssm += (size_t)r * DIi;
    yh  += (size_t)r * 256;
    yl  += (size_t)r * 256;

    int c = threadIdx.x;
    int warp = c >> 5, lane = c & 31;
    int b = blockIdx.x;

    for (int i = c; i < 40 * DIi; i += 256) sW[i] = xw[i];

    float dtwr[DTRr];
#pragma unroll
    for (int q = 0; q < DTRr; ++q) dtwr[q] = dtw[c * DTRr + q];
    float dtbr = dtb[c];
    float cw0 = cw[c * 4 + 0], cw1 = cw[c * 4 + 1], cw2 = cw[c * 4 + 2], cw3 = cw[c * 4 + 3];
    float cbr = cb[c];
    float dss = dssm[c];

    float a[NSTn];
#pragma unroll
    for (int n = 0; n < NSTn; ++n) a[n] = -__expf(alog[c * NSTn + n]);
    float a0 = a[0];
    bool geom = true;
#pragma unroll
    for (int n = 1; n < NSTn; ++n)
        geom = geom && (fabsf(a[n] - (float)(n + 1) * a0) <= 1e-4f * fabsf(a[n]));
    float h[NSTn];
#pragma unroll
    for (int n = 0; n < NSTn; ++n) h[n] = 0.f;

    __syncthreads();

    size_t base = (size_t)b * slen;
    int s0 = rev ? slen - 1 : 0;
    float xi_nx = xz[(base + s0) * xzs + c];
    float z_nx  = xz[(base + s0) * xzs + DIi + c];
    float r0 = 0.f, r1 = 0.f, r2 = 0.f, r3 = 0.f;

    for (int step = 0; step < slen; ++step) {
        int s = rev ? slen - 1 - step : step;
        r0 = r1; r1 = r2; r2 = r3; r3 = xi_nx;
        float zv = z_nx;
        if (step + 1 < slen) {
            int sn = rev ? s - 1 : s + 1;
            xi_nx = xz[(base + sn) * xzs + c];
            z_nx  = xz[(base + sn) * xzs + DIi + c];
        }
        float acc = fmaf(cw0, r0, fmaf(cw1, r1, fmaf(cw2, r2, fmaf(cw3, r3, cbr))));
        float uv = acc / (1.f + __expf(-acc));
        su[c] = uv;
        __syncthreads();
#pragma unroll
        for (int oo = 0; oo < 5; ++oo) {
            int o = warp * 5 + oo;
            const float* wr = &sW[o * DIi];
            float p = 0.f;
#pragma unroll
            for (int k8 = 0; k8 < 8; ++k8)
                p = fmaf(su[lane + 32 * k8], wr[lane + 32 * k8], p);
#pragma unroll
            for (int off = 16; off; off >>= 1) p += __shfl_xor_sync(0xffffffffu, p, off);
            if (lane == 0) sx[o] = p;
        }
        __syncthreads();
        float dtacc = dtbr;
#pragma unroll
        for (int q = 0; q < DTRr; ++q) dtacc = fmaf(sx[q], dtwr[q], dtacc);
        float dtv = (dtacc > 20.f) ? dtacc : __logf(1.f + __expf(dtacc));
        float du = dtv * uv;
        float ysum = 0.f;
        if (geom) {
            float w = __expf(dtv * a0);
            float e = 1.f;
#pragma unroll
            for (int n = 0; n < NSTn; ++n) {
                e *= w;
                h[n] = fmaf(h[n], e, du * sx[8 + n]);
                ysum = fmaf(h[n], sx[24 + n], ysum);
            }
        } else {
#pragma unroll
            for (int n = 0; n < NSTn; ++n) {
                float e = __expf(dtv * a[n]);
                h[n] = fmaf(h[n], e, du * sx[8 + n]);
                ysum = fmaf(h[n], sx[24 + n], ysum);
            }
        }
        float sg = 1.f / (1.f + __expf(-zv));
        float yv = (ysum + uv * dss) * (zv * sg);
        size_t yo = (base + s) * ystr + c;
        bsplit(yv, yh[yo], yl[yo]);
    }
}

// ======================= fused combine + LN (+transpose), bf16-split out ==========
struct P5 { const float* p[5]; };

template <int TRANS>
__global__ void k_combineln(P5 pa, int na, const float* __restrict__ ra,
                            P5 pb, int nb, const float* __restrict__ rb,
                            const float* __restrict__ w, const float* __restrict__ bia,
                            float* __restrict__ comb,
                            bf16* __restrict__ nh, bf16* __restrict__ nl) {
    __shared__ float ca[5], cb2[5];
    if (threadIdx.x == 0) {
        float mx = -1e30f;
        for (int i = 0; i < na; ++i) mx = fmaxf(mx, ra[i]);
        float s = 0.f;
        for (int i = 0; i < na; ++i) { ca[i] = __expf(ra[i] - mx); s += ca[i]; }
        for (int i = 0; i < na; ++i) ca[i] /= s;
        mx = -1e30f;
        for (int i = 0; i < nb; ++i) mx = fmaxf(mx, rb[i]);
        s = 0.f;
        for (int i = 0; i < nb; ++i) { cb2[i] = __expf(rb[i] - mx); s += cb2[i]; }
        for (int i = 0; i < nb; ++i) cb2[i] /= s;
    }
    __syncthreads();
    int warp = threadIdx.x >> 5, lane = threadIdx.x & 31;
    int row = blockIdx.x * 4 + warp;
    if (row >= TT) return;
    int irow = row;
    if (TRANS) {
        int m = row & 31;
        int bn = row >> 5;
        int n = bn % Nn, b = bn / Nn;
        irow = (b * Mm + m) * Nn + n;
    }
    float v[4];
#pragma unroll
    for (int q = 0; q < 4; ++q) {
        size_t off = (size_t)irow * Dd + lane + 32 * q;
        float acc = 0.f;
        for (int j = 0; j < na; ++j) acc = fmaf(ca[j], pa.p[j][off], acc);
        for (int j = 0; j < nb; ++j) acc = fmaf(cb2[j], pb.p[j][off], acc);
        v[q] = acc;
        comb[off] = acc;
    }
    float s = v[0] + v[1] + v[2] + v[3];
#pragma unroll
    for (int o = 16; o; o >>= 1) s += __shfl_xor_sync(0xffffffffu, s, o);
    float mu = s * (1.f / Dd);
    float q0 = 0.f;
#pragma unroll
    for (int q = 0; q < 4; ++q) { v[q] -= mu; q0 += v[q] * v[q]; }
#pragma unroll
    for (int o = 16; o; o >>= 1) q0 += __shfl_xor_sync(0xffffffffu, q0, o);
    float r = rsqrtf(q0 * (1.f / Dd) + 1e-5f);
    size_t ob = (size_t)row * Dd;
#pragma unroll
    for (int q = 0; q < 4; ++q) {
        int e = lane + 32 * q;
        bsplit(v[q] * r * w[e] + bia[e], nh[ob + e], nl[ob + e]);
    }
}

// ======================= other supporting kernels =======================

__global__ void k_stats(const float* __restrict__ x, float* __restrict__ mean,
                        float* __restrict__ stdv, float* __restrict__ xn) {
    int bm = blockIdx.x;
    int b = bm >> 5, m = bm & 31;
    int tid = threadIdx.x;
    float s = 0.f, sq = 0.f;
    for (int l = tid; l < Ll; l += 256) {
        float v = x[((size_t)b * Ll + l) * Mm + m];
        s += v; sq += v * v;
    }
    __shared__ float sh1[256], sh2[256];
    sh1[tid] = s; sh2[tid] = sq;
    __syncthreads();
    for (int o = 128; o; o >>= 1) {
        if (tid < o) { sh1[tid] += sh1[tid + o]; sh2[tid] += sh2[tid + o]; }
        __syncthreads();
    }
    __shared__ float smu, ssd;
    if (tid == 0) {
        float mu = sh1[0] / (float)Ll;
        float var = (sh2[0] - (float)Ll * mu * mu) / (float)(Ll - 1);
        if (var < 0.f) var = 0.f;
        float sd = sqrtf(var) + 1e-5f;
        smu = mu; ssd = sd;
        mean[bm] = mu; stdv[bm] = sd;
    }
    __syncthreads();
    float inv = 1.f / ssd;
    float mu = smu;
    for (int l = tid; l < Ll; l += 256) {
        xn[(size_t)bm * Ll + l] = (x[((size_t)b * Ll + l) * Mm + m] - mu) * inv;
    }
}

__global__ void k_patch(const float* __restrict__ xn, const float* __restrict__ pw,
                        const float* __restrict__ pb, const float* __restrict__ pos,
                        float* __restrict__ h) {
    int blk = blockIdx.x;
    int n = blk % Nn, bm = blk / Nn;
    int d = threadIdx.x;
    __shared__ float xs[Pp];
    if (d < Pp) xs[d] = xn[(size_t)bm * Ll + n * Sss + d];
    __syncthreads();
    float acc = pb[d];
#pragma unroll
    for (int p = 0; p < Pp; ++p) acc = fmaf(xs[p], pw[d * Pp + p], acc);
    acc += pos[n * Dd + d];
    h[(size_t)blk * Dd + d] = acc;
}

__global__ void k_ln(const float* __restrict__ x, const float* __restrict__ w,
                     const float* __restrict__ bia, float* __restrict__ out, int rows) {
    int warp = threadIdx.x >> 5, lane = threadIdx.x & 31;
    int row = blockIdx.x * 4 + warp;
    if (row >= rows) return;
    const float* xr = x + (size_t)row * Dd;
    float v0 = xr[lane], v1 = xr[lane + 32], v2 = xr[lane + 64], v3 = xr[lane + 96];
    float s = v0 + v1 + v2 + v3;
#pragma unroll
    for (int o = 16; o; o >>= 1) s += __shfl_xor_sync(0xffffffffu, s, o);
    float mu = s * (1.f / Dd);
    float d0 = v0 - mu, d1 = v1 - mu, d2 = v2 - mu, d3 = v3 - mu;
    float q = d0 * d0 + d1 * d1 + d2 * d2 + d3 * d3;
#pragma unroll
    for (int o = 16; o; o >>= 1) q += __shfl_xor_sync(0xffffffffu, q, o);
    float r = rsqrtf(q * (1.f / Dd) + 1e-5f);
    float* orow = out + (size_t)row * Dd;
    orow[lane]      = d0 * r * w[lane]      + bia[lane];
    orow[lane + 32] = d1 * r * w[lane + 32] + bia[lane + 32];
    orow[lane + 64] = d2 * r * w[lane + 64] + bia[lane + 64];
    orow[lane + 96] = d3 * r * w[lane + 96] + bia[lane + 96];
}

__global__ void k_transback(const float* __restrict__ chout, const float* __restrict__ chin,
                            float* __restrict__ out) {
    size_t total = (size_t)TT * Dd;
    for (size_t i = (size_t)blockIdx.x * blockDim.x + threadIdx.x; i < total;
         i += (size_t)gridDim.x * blockDim.x) {
        int d = (int)(i & 127);
        size_t rest = i >> 7;
        int n = (int)(rest % Nn);
        int bm = (int)(rest / Nn);
        int m = bm & 31, b = bm >> 5;
        size_t src = (((size_t)(b * Nn + n) * Mm + m) << 7) + d;
        out[i] = chout[src] + chin[i];
    }
}

// Norm2D second LN over N, bf16-split output (feeds head GEMM)
__global__ void k_ln_n(const float* __restrict__ x, const float* __restrict__ w2,
                       const float* __restrict__ b2,
                       bf16* __restrict__ oh, bf16* __restrict__ ol) {
    int idx = blockIdx.x * 256 + threadIdx.x;
    if (idx >= BMr * Dd) return;
    int d = idx & 127, bm = idx >> 7;
    const float* base = x + (size_t)bm * Nn * Dd + d;
    float s = 0.f, q = 0.f;
    for (int n = 0; n < Nn; ++n) { float v = base[(size_t)n * Dd]; s += v; q += v * v; }
    float mu = s * (1.f / Nn);
    float var = q * (1.f / Nn) - mu * mu;
    if (var < 0.f) var = 0.f;
    float r = rsqrtf(var + 1e-5f);
    size_t ob = (size_t)bm * Nn * Dd + d;
    for (int n = 0; n < Nn; ++n) {
        float v = (base[(size_t)n * Dd] - mu) * r * w2[n] + b2[n];
        bsplit(v, oh[ob + (size_t)n * Dd], ol[ob + (size_t)n * Dd]);
    }
}

__global__ void k_headred(const float* __restrict__ hp, const float* __restrict__ hb,
                          const float* __restrict__ mean, const float* __restrict__ stdv,
                          float* __restrict__ out) {
    int idx = blockIdx.x * 256 + threadIdx.x;
    if (idx >= Bb * PREDp * Mm) return;
    int m = idx % Mm;
    int p = (idx / Mm) % PREDp;
    int b = idx / (Mm * PREDp);
    int bm = b * Mm + m;
    float s = 0.f;
#pragma unroll 3
    for (int z = 0; z < KSPLIT; ++z)
        s += hp[(size_t)z * BMr * PREDp + (size_t)bm * PREDp + p];
    out[idx] = (s + hb[p]) * stdv[bm] + mean[bm];
}

// ======================= host orchestration =======================

extern "C" void kernel_launch(void* const* d_in, const int* in_sizes, int n_in,
                              void* d_out, int out_size) {
    (void)in_sizes; (void)n_in; (void)out_size;
    const float* x      = (const float*)d_in[0];
    const float* patchw = (const float*)d_in[1];
    const float* patchb = (const float*)d_in[2];
    const float* pos    = (const float*)d_in[3];
    const float* alpha  = (const float*)d_in[4];
    const float* beta   = (const float*)d_in[5];
    const float* theta  = (const float*)d_in[6];
    const float* gma    = (const float*)d_in[7];
    const float* tnw    = (const float*)d_in[8];
    const float* tnb    = (const float*)d_in[9];
    const float* cnw    = (const float*)d_in[10];
    const float* cnb    = (const float*)d_in[11];
    const float* inw    = (const float*)d_in[12];
    const float* cvw    = (const float*)d_in[13];
    const float* cvb    = (const float*)d_in[14];
    const float* xpw    = (const float*)d_in[15];
    const float* dtw    = (const float*)d_in[16];
    const float* dtbv   = (const float*)d_in[17];
    const float* alog   = (const float*)d_in[18];
    const float* dssm   = (const float*)d_in[19];
    const float* outw   = (const float*)d_in[20];
    const float* n2w1   = (const float*)d_in[21];
    const float* n2b1   = (const float*)d_in[22];
    const float* n2w2   = (const float*)d_in[23];
    const float* n2b2   = (const float*)d_in[24];
    const float* headw  = (const float*)d_in[25];
    const float* headb  = (const float*)d_in[26];

    float *p_y, *p_xn, *p_mean, *p_std, *p_tokin, *p_xz, *p_tmp, *p_chout, *p_headp;
    bf16 *p_nh, *p_nl, *p_ch, *p_cl, *p_ysh, *p_ysl;
    bf16 *p_inwh, *p_inwl, *p_outwh, *p_outwl, *p_wph, *p_wpl, *p_hdh, *p_hdl;
    cudaGetSymbolAddress((void**)&p_y,     g_y);
    cudaGetSymbolAddress((void**)&p_xn,    g_xn);
    cudaGetSymbolAddress((void**)&p_mean,  g_mean);
    cudaGetSymbolAddress((void**)&p_std,   g_std);
    cudaGetSymbolAddress((void**)&p_tokin, g_tokin);
    cudaGetSymbolAddress((void**)&p_xz,    g_xz);
    cudaGetSymbolAddress((void**)&p_tmp,   g_tmp);
    cudaGetSymbolAddress((void**)&p_chout, g_chout);
    cudaGetSymbolAddress((void**)&p_headp, g_headp);
    cudaGetSymbolAddress((void**)&p_nh,    g_nh);
    cudaGetSymbolAddress((void**)&p_nl,    g_nl);
    cudaGetSymbolAddress((void**)&p_ch,    g_ch);
    cudaGetSymbolAddress((void**)&p_cl,    g_cl);
    cudaGetSymbolAddress((void**)&p_ysh,   g_ysh);
    cudaGetSymbolAddress((void**)&p_ysl,   g_ysl);
    cudaGetSymbolAddress((void**)&p_inwh,  g_inwh);
    cudaGetSymbolAddress((void**)&p_inwl,  g_inwl);
    cudaGetSymbolAddress((void**)&p_outwh, g_outwh);
    cudaGetSymbolAddress((void**)&p_outwl, g_outwl);
    cudaGetSymbolAddress((void**)&p_wph,   g_wph);
    cudaGetSymbolAddress((void**)&p_wpl,   g_wpl);
    cudaGetSymbolAddress((void**)&p_hdh,   g_hdh);
    cudaGetSymbolAddress((void**)&p_hdl,   g_hdl);

    float* yT[5]; float* yC[5];
    yT[0] = p_y; yC[0] = p_y;
    for (int i = 1; i <= 4; ++i) {
        yT[i] = p_y + (size_t)i * TT * Dd;
        yC[i] = p_y + (size_t)(4 + i) * TT * Dd;
    }

    // weight pre-split (deterministic; runs every call)
    k_wsplit<<<768, 256>>>(inw, p_inwh, p_inwl, 4 * 3 * 512 * 128);
    k_wsplit<<<384, 256>>>(outw, p_outwh, p_outwl, 4 * 3 * 128 * 256);
    k_packsplit<<<512, 256>>>(outw, p_wph, p_wpl);
    k_wsplit<<<756, 256>>>(headw, p_hdh, p_hdl, 96 * 8064);

    k_stats<<<BMr, 256>>>(x, p_mean, p_std, p_xn);
    k_patch<<<TT, Dd>>>(p_xn, patchw, patchb, pos, p_y);

    const int GY = TT / 128;   // 252

    for (int l = 0; l < NLl; ++l) {
        // ---- token mixing ----
        P5 pa = {}, pb = {};
        for (int i = 0; i <= l; ++i) { pa.p[i] = yT[i]; pb.p[i] = yC[i]; }
        k_combineln<0><<<TT / 4, 128>>>(pa, l + 1, alpha + l * NLl,
                                        pb, l + 1, beta + l * NLl,
                                        tnw + l * Dd, tnb + l * Dd, p_tokin, p_nh, p_nl);
        {
            size_t lr = (size_t)(l * 3 + 0);
            k_mma<512><<<dim3(8, GY, 1), 256>>>(p_nh, p_nl,
                                                p_inwh + lr * 65536, p_inwl + lr * 65536,
                                                p_xz, nullptr, 128, 128, 0);
            k_fscan<<<dim3(BMr, 1), 256>>>(p_xz, 512,
                                           xpw + lr * 40 * DIi, dtw + lr * DIi * DTRr,
                                           dtbv + lr * DIi, cvw + lr * DIi * DCc,
                                           cvb + lr * DIi, alog + lr * DIi * NSTn,
                                           dssm + lr * DIi, p_ysh, p_ysl, 256, Nn);
            k_mma<128><<<dim3(2, GY, 1), 256>>>(p_ysh, p_ysl,
                                                p_outwh + lr * 32768, p_outwl + lr * 32768,
                                                yT[l + 1], p_tokin, 256, 256, 2);
        }

        // ---- channel mixing (fwd+bwd fused) ----
        P5 pc = {}, pd = {};
        for (int i = 0; i <= l + 1; ++i) pc.p[i] = yT[i];
        for (int i = 0; i <= l; ++i)     pd.p[i] = yC[i];
        k_combineln<1><<<TT / 4, 128>>>(pc, l + 2, theta + l * (NLl + 1),
                                        pd, l + 1, gma + l * NLl,
                                        cnw + l * Dd, cnb + l * Dd, p_tokin, p_ch, p_cl);
        {
            size_t lr = (size_t)(l * 3 + 1);
            k_mma<1024><<<dim3(16, GY, 1), 256>>>(p_ch, p_cl,
                                                  p_inwh + lr * 65536, p_inwl + lr * 65536,
                                                  p_xz, nullptr, 128, 128, 0);
            k_fscan<<<dim3(BNb, 2), 256>>>(p_xz, 1024,
                                           xpw + lr * 40 * DIi, dtw + lr * DIi * DTRr,
                                           dtbv + lr * DIi, cvw + lr * DIi * DCc,
                                           cvb + lr * DIi, alog + lr * DIi * NSTn,
                                           dssm + lr * DIi, p_ysh, p_ysl, 512, Mm);
            k_mma<128><<<dim3(2, GY, 1), 256>>>(p_ysh, p_ysl,
                                                p_wph + (size_t)l * 65536, p_wpl + (size_t)l * 65536,
                                                p_chout, nullptr, 512, 512, 0);
        }
        k_transback<<<4096, 256>>>(p_chout, p_tokin, yC[l + 1]);
    }

    k_ln<<<TT / 4, 128>>>(yC[4], n2w1, n2b1, p_tmp, TT);
    k_ln_n<<<(BMr * Dd + 255) / 256, 256>>>(p_tmp, n2w2, n2b2, p_nh, p_nl);
    k_mma<96><<<dim3(2, 4, KSPLIT), 256>>>(p_nh, p_nl, p_hdh, p_hdl,
                                           p_headp, nullptr, 8064, 384, 0);
    k_headred<<<(Bb * PREDp * Mm + 255) / 256, 256>>>(p_headp, headb, p_mean, p_std,
                                                      (float*)d_out);
}